// round 13
// baseline (speedup 1.0000x reference)
#include <cuda_runtime.h>

#define N_NODES 100000
#define D 64
#define NWARP 16            // warps per layer block; each warp owns 4 nodes
#define LTHREADS (NWARP*32) // 512
#define NBLK_LAYER 444      // exactly one wave: 148 SMs x 3 blocks (smem-limited)
#define NQUADS (N_NODES/4)  // 25000, exact

// dynamic smem layout (floats): WlT[4096] | WrT[4096] | bs[64] | buf[16][512]
#define SM_WLT 0
#define SM_WRT 4096
#define SM_BS  8192
#define SM_BUF 8256
#define SM_TOTAL_FLOATS (8256 + NWARP * 8 * D)   // 16448 floats = 65792 B

// ---- scratch (no allocations allowed; device globals) ----
__device__ float g_hA  [(size_t)N_NODES * D];
__device__ float g_hB  [(size_t)N_NODES * D];
__device__ int   g_degi[N_NODES];
__device__ float g_inv [N_NODES];
__device__ int   g_rowptr[N_NODES + 1];
__device__ int   g_cursor[N_NODES];
__device__ int   g_csrc[2000000];       // sorted-by-dst source ids (cap > E)
__device__ int   g_is32;

// ---- edge-index width detection (int64 requested by ref, but JAX default
// config silently downgrades to int32; decide on-device, deterministically) ----
__global__ void detect_kernel(const void* ei) {
    const long long* p = (const long long*)ei;
    int is32 = 0;
    for (int i = 0; i < 128; i++) {
        long long v = p[i];
        if (v < 0 || v >= N_NODES) { is32 = 1; break; }
    }
    g_is32 = is32;
}

__device__ __forceinline__ int load_idx(const void* ei, long long i, int is32) {
    return is32 ? ((const int*)ei)[i] : (int)((const long long*)ei)[i];
}

// ---- CSR build: 4 edges per thread, vectorized index loads ----
// vec4 path valid when E % 4 == 0 (16B alignment of the dst sub-array).
__global__ void degree_kernel(const void* __restrict__ ei, int E, int vec4) {
    int t = blockIdx.x * blockDim.x + threadIdx.x;
    int is32 = g_is32;
    if (vec4) {
        int e = t * 4;
        if (e >= E) return;
        int d0, d1, d2, d3;
        if (is32) {
            int4 dv = ((const int4*)((const int*)ei + E))[t];
            d0 = dv.x; d1 = dv.y; d2 = dv.z; d3 = dv.w;
        } else {
            longlong2 a = ((const longlong2*)((const long long*)ei + E))[t * 2];
            longlong2 b = ((const longlong2*)((const long long*)ei + E))[t * 2 + 1];
            d0 = (int)a.x; d1 = (int)a.y; d2 = (int)b.x; d3 = (int)b.y;
        }
        atomicAdd(&g_degi[d0], 1);
        atomicAdd(&g_degi[d1], 1);
        atomicAdd(&g_degi[d2], 1);
        atomicAdd(&g_degi[d3], 1);
    } else {
        if (t >= E) return;
        int d = load_idx(ei, (long long)E + t, is32);
        atomicAdd(&g_degi[d], 1);
    }
}

// single-block exclusive scan via warp shuffles (1024 threads, chunked)
__global__ void scan_kernel() {
    __shared__ int wsum[32];
    __shared__ int s_carry;
    int tid = threadIdx.x, lane = tid & 31, wid = tid >> 5;
    if (tid == 0) s_carry = 0;
    __syncthreads();
    for (int base = 0; base < N_NODES; base += 1024) {
        int i = base + tid;
        int v = (i < N_NODES) ? g_degi[i] : 0;
        int s = v;
#pragma unroll
        for (int off = 1; off < 32; off <<= 1) {
            int t = __shfl_up_sync(0xffffffffu, s, off);
            if (lane >= off) s += t;
        }
        if (lane == 31) wsum[wid] = s;
        __syncthreads();
        if (wid == 0) {
            int w = wsum[lane];
#pragma unroll
            for (int off = 1; off < 32; off <<= 1) {
                int t = __shfl_up_sync(0xffffffffu, w, off);
                if (lane >= off) w += t;
            }
            wsum[lane] = w;
        }
        __syncthreads();
        int carry = s_carry;
        int incl = s + (wid > 0 ? wsum[wid - 1] : 0) + carry;
        if (i < N_NODES) {
            int excl = incl - v;
            g_rowptr[i] = excl;
            g_cursor[i] = excl;
            g_inv[i]    = 1.0f / fmaxf((float)v, 1.0f);
        }
        __syncthreads();
        if (tid == 1023) s_carry = incl;
        __syncthreads();
    }
    if (threadIdx.x == 0) g_rowptr[N_NODES] = s_carry;
}

__global__ void fill_kernel(const void* __restrict__ ei, int E, int vec4) {
    int t = blockIdx.x * blockDim.x + threadIdx.x;
    int is32 = g_is32;
    if (vec4) {
        int e = t * 4;
        if (e >= E) return;
        int s0, s1, s2, s3, d0, d1, d2, d3;
        if (is32) {
            int4 sv = ((const int4*)ei)[t];
            int4 dv = ((const int4*)((const int*)ei + E))[t];
            s0 = sv.x; s1 = sv.y; s2 = sv.z; s3 = sv.w;
            d0 = dv.x; d1 = dv.y; d2 = dv.z; d3 = dv.w;
        } else {
            longlong2 sa = ((const longlong2*)ei)[t * 2];
            longlong2 sb = ((const longlong2*)ei)[t * 2 + 1];
            longlong2 da = ((const longlong2*)((const long long*)ei + E))[t * 2];
            longlong2 db = ((const longlong2*)((const long long*)ei + E))[t * 2 + 1];
            s0 = (int)sa.x; s1 = (int)sa.y; s2 = (int)sb.x; s3 = (int)sb.y;
            d0 = (int)da.x; d1 = (int)da.y; d2 = (int)db.x; d3 = (int)db.y;
        }
        g_csrc[atomicAdd(&g_cursor[d0], 1)] = s0;
        g_csrc[atomicAdd(&g_cursor[d1], 1)] = s1;
        g_csrc[atomicAdd(&g_cursor[d2], 1)] = s2;
        g_csrc[atomicAdd(&g_cursor[d3], 1)] = s3;
    } else {
        if (t >= E) return;
        int s = load_idx(ei, t, is32);
        int d = load_idx(ei, (long long)E + t, is32);
        g_csrc[atomicAdd(&g_cursor[d], 1)] = s;
    }
}

// ---- fused layer: mean-gather + dual matvec + bias (+relu) ----
// Warp owns FOUR consecutive nodes: gather all four, then ONE matvec pass
// loading each smem weight value once for 4 nodes -> weight LDS per node
// is 4x lower than naive; matvec sits at the FMA issue floor.
// Gather: half-warp per neighbor, lane reads float4 (LDG.128); 8 nbrs/iter
// main loop, then 4-nbr and 2-nbr tail steps to keep MLP>=2 in remainders.
// Dynamic smem: weights (stride 64, hot reads are conflict-free full rows).
__global__ __launch_bounds__(LTHREADS)
void layer_kernel(const float* __restrict__ hin,
                  const float* __restrict__ Wl,
                  const float* __restrict__ Wr,
                  const float* __restrict__ b,
                  float* __restrict__ hout, int relu) {
    extern __shared__ float sm[];
    float* WlT = sm + SM_WLT;            // [k*64 + j]
    float* WrT = sm + SM_WRT;
    float* bs  = sm + SM_BS;
    float* buf = sm + SM_BUF;            // [warp][u*2*D + {agg|x}]

    int tid = threadIdx.x;
    for (int i = tid; i < D * D; i += LTHREADS) {
        int j = i >> 6, k = i & 63;      // W[j,k] -> WT[k*64+j]
        WlT[k * D + j] = Wl[i];          // (one-time strided write; conflicts OK)
        WrT[k * D + j] = Wr[i];
    }
    if (tid < D) bs[tid] = b[tid];
    __syncthreads();

    int warp = tid >> 5, lane = tid & 31;
    int half = lane >> 4;     // which neighbor of the pair this lane serves
    int q    = lane & 15;     // float4 slot within the 256B row
    float* mybuf = buf + warp * 8 * D;

    for (int p = blockIdx.x * NWARP + warp; p < NQUADS;
         p += NBLK_LAYER * NWARP) {
        int n0 = 4 * p;

        // ---- gather all four nodes (mean aggregation into buf) ----
#pragma unroll
        for (int u = 0; u < 4; u++) {
            int n = n0 + u;
            int start = g_rowptr[n], end = g_rowptr[n + 1];
            float inv = g_inv[n];
            float2 xv = ((const float2*)(hin + (long long)n * D))[lane];

            float4 aA = make_float4(0.f, 0.f, 0.f, 0.f);
            float4 aB = make_float4(0.f, 0.f, 0.f, 0.f);
            float4 aC = make_float4(0.f, 0.f, 0.f, 0.f);
            float4 aD = make_float4(0.f, 0.f, 0.f, 0.f);
            int i = start;
            for (; i + 8 <= end; i += 8) {
                int s0 = g_csrc[i + half];
                int s1 = g_csrc[i + 2 + half];
                int s2 = g_csrc[i + 4 + half];
                int s3 = g_csrc[i + 6 + half];
                float4 v0 = ((const float4*)(hin + (long long)s0 * D))[q];
                float4 v1 = ((const float4*)(hin + (long long)s1 * D))[q];
                float4 v2 = ((const float4*)(hin + (long long)s2 * D))[q];
                float4 v3 = ((const float4*)(hin + (long long)s3 * D))[q];
                aA.x += v0.x; aA.y += v0.y; aA.z += v0.z; aA.w += v0.w;
                aB.x += v1.x; aB.y += v1.y; aB.z += v1.z; aB.w += v1.w;
                aC.x += v2.x; aC.y += v2.y; aC.z += v2.z; aC.w += v2.w;
                aD.x += v3.x; aD.y += v3.y; aD.z += v3.z; aD.w += v3.w;
            }
            if (i + 4 <= end) {            // 4-nbr tail: 2 loads in flight
                int s0 = g_csrc[i + half];
                int s1 = g_csrc[i + 2 + half];
                float4 v0 = ((const float4*)(hin + (long long)s0 * D))[q];
                float4 v1 = ((const float4*)(hin + (long long)s1 * D))[q];
                aA.x += v0.x; aA.y += v0.y; aA.z += v0.z; aA.w += v0.w;
                aB.x += v1.x; aB.y += v1.y; aB.z += v1.z; aB.w += v1.w;
                i += 4;
            }
            if (i + 2 <= end) {            // 2-nbr tail
                int s0 = g_csrc[i + half];
                float4 v0 = ((const float4*)(hin + (long long)s0 * D))[q];
                aA.x += v0.x; aA.y += v0.y; aA.z += v0.z; aA.w += v0.w;
                i += 2;
            }
            if (i < end && half == 0) {    // odd last neighbor
                int s0 = g_csrc[i];
                float4 v0 = ((const float4*)(hin + (long long)s0 * D))[q];
                aA.x += v0.x; aA.y += v0.y; aA.z += v0.z; aA.w += v0.w;
            }
            float4 ac;
            ac.x = (aA.x + aB.x) + (aC.x + aD.x);
            ac.y = (aA.y + aB.y) + (aC.y + aD.y);
            ac.z = (aA.z + aB.z) + (aC.z + aD.z);
            ac.w = (aA.w + aB.w) + (aC.w + aD.w);
            ac.x += __shfl_xor_sync(0xffffffffu, ac.x, 16);
            ac.y += __shfl_xor_sync(0xffffffffu, ac.y, 16);
            ac.z += __shfl_xor_sync(0xffffffffu, ac.z, 16);
            ac.w += __shfl_xor_sync(0xffffffffu, ac.w, 16);

            if (half == 0) {
                float4 agg4;
                agg4.x = ac.x * inv; agg4.y = ac.y * inv;
                agg4.z = ac.z * inv; agg4.w = ac.w * inv;
                ((float4*)&mybuf[u * 2 * D])[q] = agg4;
            }
            ((float2*)&mybuf[u * 2 * D + D])[lane] = xv;
        }
        __syncwarp();

        // ---- matvec for all FOUR nodes; each weight value loaded once ----
        float2 acc0 = *(const float2*)&bs[2 * lane];
        float2 acc1 = acc0, acc2 = acc0, acc3 = acc0;
#pragma unroll
        for (int k2 = 0; k2 < D / 2; k2++) {
            int k = 2 * k2;
            float2 wl0 = *(const float2*)&WlT[k * D + 2 * lane];
            float2 wr0 = *(const float2*)&WrT[k * D + 2 * lane];
            float2 wl1 = *(const float2*)&WlT[(k + 1) * D + 2 * lane];
            float2 wr1 = *(const float2*)&WrT[(k + 1) * D + 2 * lane];
            float2 m0 = ((const float2*)&mybuf[0])[k2];
            float2 x0 = ((const float2*)&mybuf[D])[k2];
            float2 m1 = ((const float2*)&mybuf[2 * D])[k2];
            float2 x1 = ((const float2*)&mybuf[3 * D])[k2];
            float2 m2 = ((const float2*)&mybuf[4 * D])[k2];
            float2 x2 = ((const float2*)&mybuf[5 * D])[k2];
            float2 m3 = ((const float2*)&mybuf[6 * D])[k2];
            float2 x3 = ((const float2*)&mybuf[7 * D])[k2];
            acc0.x = fmaf(m0.x, wl0.x, acc0.x); acc0.y = fmaf(m0.x, wl0.y, acc0.y);
            acc0.x = fmaf(x0.x, wr0.x, acc0.x); acc0.y = fmaf(x0.x, wr0.y, acc0.y);
            acc0.x = fmaf(m0.y, wl1.x, acc0.x); acc0.y = fmaf(m0.y, wl1.y, acc0.y);
            acc0.x = fmaf(x0.y, wr1.x, acc0.x); acc0.y = fmaf(x0.y, wr1.y, acc0.y);
            acc1.x = fmaf(m1.x, wl0.x, acc1.x); acc1.y = fmaf(m1.x, wl0.y, acc1.y);
            acc1.x = fmaf(x1.x, wr0.x, acc1.x); acc1.y = fmaf(x1.x, wr0.y, acc1.y);
            acc1.x = fmaf(m1.y, wl1.x, acc1.x); acc1.y = fmaf(m1.y, wl1.y, acc1.y);
            acc1.x = fmaf(x1.y, wr1.x, acc1.x); acc1.y = fmaf(x1.y, wr1.y, acc1.y);
            acc2.x = fmaf(m2.x, wl0.x, acc2.x); acc2.y = fmaf(m2.x, wl0.y, acc2.y);
            acc2.x = fmaf(x2.x, wr0.x, acc2.x); acc2.y = fmaf(x2.x, wr0.y, acc2.y);
            acc2.x = fmaf(m2.y, wl1.x, acc2.x); acc2.y = fmaf(m2.y, wl1.y, acc2.y);
            acc2.x = fmaf(x2.y, wr1.x, acc2.x); acc2.y = fmaf(x2.y, wr1.y, acc2.y);
            acc3.x = fmaf(m3.x, wl0.x, acc3.x); acc3.y = fmaf(m3.x, wl0.y, acc3.y);
            acc3.x = fmaf(x3.x, wr0.x, acc3.x); acc3.y = fmaf(x3.x, wr0.y, acc3.y);
            acc3.x = fmaf(m3.y, wl1.x, acc3.x); acc3.y = fmaf(m3.y, wl1.y, acc3.y);
            acc3.x = fmaf(x3.y, wr1.x, acc3.x); acc3.y = fmaf(x3.y, wr1.y, acc3.y);
        }
        if (relu) {
            acc0.x = fmaxf(acc0.x, 0.f); acc0.y = fmaxf(acc0.y, 0.f);
            acc1.x = fmaxf(acc1.x, 0.f); acc1.y = fmaxf(acc1.y, 0.f);
            acc2.x = fmaxf(acc2.x, 0.f); acc2.y = fmaxf(acc2.y, 0.f);
            acc3.x = fmaxf(acc3.x, 0.f); acc3.y = fmaxf(acc3.y, 0.f);
        }
        ((float2*)(hout + (long long)n0 * D))[lane] = acc0;
        ((float2*)(hout + (long long)(n0 + 1) * D))[lane] = acc1;
        ((float2*)(hout + (long long)(n0 + 2) * D))[lane] = acc2;
        ((float2*)(hout + (long long)(n0 + 3) * D))[lane] = acc3;
        __syncwarp();   // buf reused next iteration
    }
}

extern "C" void kernel_launch(void* const* d_in, const int* in_sizes, int n_in,
                              void* d_out, int out_size) {
    const float* x   = (const float*)d_in[0];
    const void*  ei  = d_in[1];
    const float* Wl0 = (const float*)d_in[2];
    const float* Wr0 = (const float*)d_in[3];
    const float* b0  = (const float*)d_in[4];
    const float* Wl1 = (const float*)d_in[5];
    const float* Wr1 = (const float*)d_in[6];
    const float* b1  = (const float*)d_in[7];
    const float* Wl2 = (const float*)d_in[8];
    const float* Wr2 = (const float*)d_in[9];
    const float* b2  = (const float*)d_in[10];
    float* out = (float*)d_out;

    int E = in_sizes[1] / 2;
    int vec4 = (E % 4 == 0);
    const int SMEM_BYTES = SM_TOTAL_FLOATS * sizeof(float);   // ~65.8 KB

    cudaFuncSetAttribute(layer_kernel,
                         cudaFuncAttributeMaxDynamicSharedMemorySize,
                         SMEM_BYTES);

    void *degp, *hAp, *hBp;
    cudaGetSymbolAddress(&degp, g_degi);
    cudaGetSymbolAddress(&hAp,  g_hA);
    cudaGetSymbolAddress(&hBp,  g_hB);
    float* hA = (float*)hAp;
    float* hB = (float*)hBp;

    const int TB = 256;
    int nwork = vec4 ? (E / 4) : E;
    int edge_blocks = (nwork + TB - 1) / TB;

    // ---- CSR build (once per call; graph-capturable, deterministic work) ----
    cudaMemsetAsync(degp, 0, N_NODES * sizeof(int));
    detect_kernel<<<1, 1>>>(ei);
    degree_kernel<<<edge_blocks, TB>>>(ei, E, vec4);
    scan_kernel<<<1, 1024>>>();
    fill_kernel<<<edge_blocks, TB>>>(ei, E, vec4);

    // ---- 3 fused layers ----
    layer_kernel<<<NBLK_LAYER, LTHREADS, SMEM_BYTES>>>(x,  Wl0, Wr0, b0, hA,  1);
    layer_kernel<<<NBLK_LAYER, LTHREADS, SMEM_BYTES>>>(hA, Wl1, Wr1, b1, hB,  1);
    layer_kernel<<<NBLK_LAYER, LTHREADS, SMEM_BYTES>>>(hB, Wl2, Wr2, b2, out, 0);
}

// round 16
// speedup vs baseline: 1.6646x; 1.6646x over previous
#include <cuda_runtime.h>

#define N_NODES 100000
#define D 64
#define NWARP 16            // warps per layer block; each warp owns 4 nodes
#define LTHREADS (NWARP*32) // 512
#define NBLK_LAYER 296      // one wave: 148 SMs x 2 blocks (smem-limited)
#define NQUADS (N_NODES/4)  // 25000, exact
#define NSB 98              // scan blocks: ceil(100000/1024)

// dynamic smem (floats): WlD[8192] | WrD[8192] | bsd[128] | buf[16][512]
// WlD/WrD: duplicated weights, [k][2j],[2j+1] = W[j][k]  (packed-FMA operand)
// bsd: duplicated bias {b_j, b_j}
// buf per warp: pair01 {m interleaved[128] | x interleaved[128]} then pair23
#define SM_WLD 0
#define SM_WRD 8192
#define SM_BSD 16384
#define SM_BUF 16512
#define SM_TOTAL_FLOATS (16512 + NWARP * 512)   // 24704 floats = 98816 B

typedef unsigned long long ull;

__device__ __forceinline__ ull fma2(ull a, ull b, ull c) {
    ull d;
    asm("fma.rn.f32x2 %0, %1, %2, %3;" : "=l"(d) : "l"(a), "l"(b), "l"(c));
    return d;
}
__device__ __forceinline__ float2 unpack2(ull v) {
    float2 r;
    asm("mov.b64 {%0, %1}, %2;" : "=f"(r.x), "=f"(r.y) : "l"(v));
    return r;
}

// ---- scratch (no allocations allowed; device globals) ----
__device__ float g_hA  [(size_t)N_NODES * D];
__device__ float g_hB  [(size_t)N_NODES * D];
__device__ int   g_degi[N_NODES];
__device__ float g_inv [N_NODES];
__device__ int   g_rowptr[N_NODES + 4];   // padded so int4 tail reads are safe
__device__ int   g_cursor[N_NODES];
__device__ int   g_bsum[128];
__device__ int   g_boff[128];
__device__ int   g_csrc[2000000];       // sorted-by-dst source ids (cap > E)
__device__ int   g_is32;

// ---- edge-index width detection (warp-parallel ballot) ----
__global__ void detect_kernel(const void* ei) {
    const long long* p = (const long long*)ei;
    int lane = threadIdx.x;
    int bad = 0;
    for (int i = lane; i < 128; i += 32) {
        long long v = p[i];
        if (v < 0 || v >= N_NODES) bad = 1;
    }
    unsigned m = __ballot_sync(0xffffffffu, bad);
    if (lane == 0) g_is32 = (m != 0);
}

__device__ __forceinline__ int load_idx(const void* ei, long long i, int is32) {
    return is32 ? ((const int*)ei)[i] : (int)((const long long*)ei)[i];
}

// ---- CSR build: 4 edges per thread, vectorized index loads ----
__global__ void degree_kernel(const void* __restrict__ ei, int E, int vec4) {
    int t = blockIdx.x * blockDim.x + threadIdx.x;
    int is32 = g_is32;
    if (vec4) {
        int e = t * 4;
        if (e >= E) return;
        int d0, d1, d2, d3;
        if (is32) {
            int4 dv = ((const int4*)((const int*)ei + E))[t];
            d0 = dv.x; d1 = dv.y; d2 = dv.z; d3 = dv.w;
        } else {
            longlong2 a = ((const longlong2*)((const long long*)ei + E))[t * 2];
            longlong2 b = ((const longlong2*)((const long long*)ei + E))[t * 2 + 1];
            d0 = (int)a.x; d1 = (int)a.y; d2 = (int)b.x; d3 = (int)b.y;
        }
        atomicAdd(&g_degi[d0], 1);
        atomicAdd(&g_degi[d1], 1);
        atomicAdd(&g_degi[d2], 1);
        atomicAdd(&g_degi[d3], 1);
    } else {
        if (t >= E) return;
        int d = load_idx(ei, (long long)E + t, is32);
        atomicAdd(&g_degi[d], 1);
    }
}

// ---- hierarchical scan (3 parallel stages) ----
__global__ void scan1_kernel() {
    __shared__ int wsum[32];
    int tid = threadIdx.x, lane = tid & 31, wid = tid >> 5;
    int i = blockIdx.x * 1024 + tid;
    int v = (i < N_NODES) ? g_degi[i] : 0;
    int s = v;
#pragma unroll
    for (int off = 1; off < 32; off <<= 1) {
        int t = __shfl_up_sync(0xffffffffu, s, off);
        if (lane >= off) s += t;
    }
    if (lane == 31) wsum[wid] = s;
    __syncthreads();
    if (wid == 0) {
        int w = wsum[lane];
#pragma unroll
        for (int off = 1; off < 32; off <<= 1) {
            int t = __shfl_up_sync(0xffffffffu, w, off);
            if (lane >= off) w += t;
        }
        wsum[lane] = w;
    }
    __syncthreads();
    int incl = s + (wid ? wsum[wid - 1] : 0);
    if (i < N_NODES) g_rowptr[i] = incl - v;     // local exclusive
    if (tid == 1023) g_bsum[blockIdx.x] = incl;  // block total
}

__global__ void scan2_kernel(int nb) {
    __shared__ int wsum[4];
    int t = threadIdx.x, lane = t & 31, wid = t >> 5;
    int v = (t < nb) ? g_bsum[t] : 0;
    int s = v;
#pragma unroll
    for (int off = 1; off < 32; off <<= 1) {
        int x = __shfl_up_sync(0xffffffffu, s, off);
        if (lane >= off) s += x;
    }
    if (lane == 31) wsum[wid] = s;
    __syncthreads();
    if (t == 0) {
        int c = 0;
        for (int w = 0; w < 4; w++) { int x = wsum[w]; wsum[w] = c; c += x; }
    }
    __syncthreads();
    int excl = wsum[wid] + s - v;
    if (t < nb) g_boff[t] = excl;
    if (t == nb - 1) {                      // total = E, replicate into pad
        int tot = excl + v;
        g_rowptr[N_NODES]     = tot;
        g_rowptr[N_NODES + 1] = tot;
        g_rowptr[N_NODES + 2] = tot;
        g_rowptr[N_NODES + 3] = tot;
    }
}

__global__ void scan3_kernel() {
    int i = blockIdx.x * 1024 + threadIdx.x;
    if (i >= N_NODES) return;
    int r = g_rowptr[i] + g_boff[blockIdx.x];
    g_rowptr[i] = r;
    g_cursor[i] = r;
    g_inv[i] = 1.0f / fmaxf((float)g_degi[i], 1.0f);
}

__global__ void fill_kernel(const void* __restrict__ ei, int E, int vec4) {
    int t = blockIdx.x * blockDim.x + threadIdx.x;
    int is32 = g_is32;
    if (vec4) {
        int e = t * 4;
        if (e >= E) return;
        int s0, s1, s2, s3, d0, d1, d2, d3;
        if (is32) {
            int4 sv = ((const int4*)ei)[t];
            int4 dv = ((const int4*)((const int*)ei + E))[t];
            s0 = sv.x; s1 = sv.y; s2 = sv.z; s3 = sv.w;
            d0 = dv.x; d1 = dv.y; d2 = dv.z; d3 = dv.w;
        } else {
            longlong2 sa = ((const longlong2*)ei)[t * 2];
            longlong2 sb = ((const longlong2*)ei)[t * 2 + 1];
            longlong2 da = ((const longlong2*)((const long long*)ei + E))[t * 2];
            longlong2 db = ((const longlong2*)((const long long*)ei + E))[t * 2 + 1];
            s0 = (int)sa.x; s1 = (int)sa.y; s2 = (int)sb.x; s3 = (int)sb.y;
            d0 = (int)da.x; d1 = (int)da.y; d2 = (int)db.x; d3 = (int)db.y;
        }
        g_csrc[atomicAdd(&g_cursor[d0], 1)] = s0;
        g_csrc[atomicAdd(&g_cursor[d1], 1)] = s1;
        g_csrc[atomicAdd(&g_cursor[d2], 1)] = s2;
        g_csrc[atomicAdd(&g_cursor[d3], 1)] = s3;
    } else {
        if (t >= E) return;
        int s = load_idx(ei, t, is32);
        int d = load_idx(ei, (long long)E + t, is32);
        g_csrc[atomicAdd(&g_cursor[d], 1)] = s;
    }
}

// ---- fused layer: mean-gather + packed-f32x2 dual matvec + bias (+relu) ----
// Warp owns FOUR nodes as two f32x2-packed PAIRS: lane's packed acc holds
// {node_even, node_odd}. Features stored interleaved in smem -> one broadcast
// LDS.64 = packed operand. Weights duplicated {w,w} -> per-lane LDS.64,
// conflict-free (lane -> outputs j=lane, j=lane+32). FFMA2 halves FMA-pipe
// work vs scalar fp32. Quad metadata (rowptr/inv) prefetched vectorized.
__global__ __launch_bounds__(LTHREADS, 2)
void layer_kernel(const float* __restrict__ hin,
                  const float* __restrict__ Wl,
                  const float* __restrict__ Wr,
                  const float* __restrict__ b,
                  float* __restrict__ hout, int relu) {
    extern __shared__ float sm[];
    float* WlD = sm + SM_WLD;
    float* WrD = sm + SM_WRD;
    float* bsd = sm + SM_BSD;
    float* buf = sm + SM_BUF;

    int tid = threadIdx.x;
    for (int i = tid; i < D * D; i += LTHREADS) {
        int j = i >> 6, k = i & 63;      // W[j,k]
        float wl = Wl[i], wr = Wr[i];
        WlD[k * 128 + 2 * j]     = wl;
        WlD[k * 128 + 2 * j + 1] = wl;
        WrD[k * 128 + 2 * j]     = wr;
        WrD[k * 128 + 2 * j + 1] = wr;
    }
    if (tid < D) { bsd[2 * tid] = b[tid]; bsd[2 * tid + 1] = b[tid]; }
    __syncthreads();

    int warp = tid >> 5, lane = tid & 31;
    int half = lane >> 4;     // which neighbor of the pair this lane serves
    int q    = lane & 15;     // float4 slot within the 256B row
    float* mybuf = buf + warp * 512;

    for (int p = blockIdx.x * NWARP + warp; p < NQUADS;
         p += NBLK_LAYER * NWARP) {
        int n0 = 4 * p;

        // prefetch quad-uniform metadata (vectorized; n0 is 16B-aligned)
        int4  rp4  = *(const int4*)&g_rowptr[n0];
        int   rp4e = g_rowptr[n0 + 4];
        float4 inv4 = *(const float4*)&g_inv[n0];
        int rps[5] = {rp4.x, rp4.y, rp4.z, rp4.w, rp4e};
        float invs[4] = {inv4.x, inv4.y, inv4.z, inv4.w};

        // ---- gather 4 nodes; write mean + self interleaved into buf ----
#pragma unroll
        for (int u = 0; u < 4; u++) {
            int n = n0 + u;
            int c  = u & 1;               // slot within the packed pair
            int pb = (u >> 1) * 256;      // pair01 at 0, pair23 at 256
            int start = rps[u], end = rps[u + 1];
            float inv = invs[u];
            float2 xv = ((const float2*)(hin + (long long)n * D))[lane];

            float4 aA = make_float4(0.f, 0.f, 0.f, 0.f);
            float4 aB = make_float4(0.f, 0.f, 0.f, 0.f);
            float4 aC = make_float4(0.f, 0.f, 0.f, 0.f);
            float4 aD = make_float4(0.f, 0.f, 0.f, 0.f);
            int i = start;
            for (; i + 8 <= end; i += 8) {
                int s0 = g_csrc[i + half];
                int s1 = g_csrc[i + 2 + half];
                int s2 = g_csrc[i + 4 + half];
                int s3 = g_csrc[i + 6 + half];
                float4 v0 = ((const float4*)(hin + (long long)s0 * D))[q];
                float4 v1 = ((const float4*)(hin + (long long)s1 * D))[q];
                float4 v2 = ((const float4*)(hin + (long long)s2 * D))[q];
                float4 v3 = ((const float4*)(hin + (long long)s3 * D))[q];
                aA.x += v0.x; aA.y += v0.y; aA.z += v0.z; aA.w += v0.w;
                aB.x += v1.x; aB.y += v1.y; aB.z += v1.z; aB.w += v1.w;
                aC.x += v2.x; aC.y += v2.y; aC.z += v2.z; aC.w += v2.w;
                aD.x += v3.x; aD.y += v3.y; aD.z += v3.z; aD.w += v3.w;
            }
            if (i + 4 <= end) {
                int s0 = g_csrc[i + half];
                int s1 = g_csrc[i + 2 + half];
                float4 v0 = ((const float4*)(hin + (long long)s0 * D))[q];
                float4 v1 = ((const float4*)(hin + (long long)s1 * D))[q];
                aA.x += v0.x; aA.y += v0.y; aA.z += v0.z; aA.w += v0.w;
                aB.x += v1.x; aB.y += v1.y; aB.z += v1.z; aB.w += v1.w;
                i += 4;
            }
            if (i + 2 <= end) {
                int s0 = g_csrc[i + half];
                float4 v0 = ((const float4*)(hin + (long long)s0 * D))[q];
                aA.x += v0.x; aA.y += v0.y; aA.z += v0.z; aA.w += v0.w;
                i += 2;
            }
            if (i < end && half == 0) {
                int s0 = g_csrc[i];
                float4 v0 = ((const float4*)(hin + (long long)s0 * D))[q];
                aA.x += v0.x; aA.y += v0.y; aA.z += v0.z; aA.w += v0.w;
            }
            float4 ac;
            ac.x = (aA.x + aB.x) + (aC.x + aD.x);
            ac.y = (aA.y + aB.y) + (aC.y + aD.y);
            ac.z = (aA.z + aB.z) + (aC.z + aD.z);
            ac.w = (aA.w + aB.w) + (aC.w + aD.w);
            ac.x += __shfl_xor_sync(0xffffffffu, ac.x, 16);
            ac.y += __shfl_xor_sync(0xffffffffu, ac.y, 16);
            ac.z += __shfl_xor_sync(0xffffffffu, ac.z, 16);
            ac.w += __shfl_xor_sync(0xffffffffu, ac.w, 16);

            if (half == 0) {    // dims 4q..4q+3, interleaved slots {2*dim + c}
                mybuf[pb + 8 * q + 0 + c] = ac.x * inv;
                mybuf[pb + 8 * q + 2 + c] = ac.y * inv;
                mybuf[pb + 8 * q + 4 + c] = ac.z * inv;
                mybuf[pb + 8 * q + 6 + c] = ac.w * inv;
            }
            mybuf[pb + 128 + 4 * lane + 0 + c] = xv.x;   // dims 2l, 2l+1
            mybuf[pb + 128 + 4 * lane + 2 + c] = xv.y;
        }
        __syncwarp();

        // ---- packed matvec: lane -> outputs j=lane, j=lane+32 ----
        ull A00 = *(const ull*)&bsd[2 * lane];         // j=lane,    pair01
        ull A10 = *(const ull*)&bsd[2 * lane + 64];    // j=lane+32, pair01
        ull A01 = A00;                                  // j=lane,    pair23
        ull A11 = A10;                                  // j=lane+32, pair23
#pragma unroll
        for (int k = 0; k < D; k += 2) {
            ull mA0 = *(const ull*)&mybuf[2 * k];
            ull mB0 = *(const ull*)&mybuf[2 * k + 2];
            ull xA0 = *(const ull*)&mybuf[128 + 2 * k];
            ull xB0 = *(const ull*)&mybuf[128 + 2 * k + 2];
            ull mA1 = *(const ull*)&mybuf[256 + 2 * k];
            ull mB1 = *(const ull*)&mybuf[256 + 2 * k + 2];
            ull xA1 = *(const ull*)&mybuf[384 + 2 * k];
            ull xB1 = *(const ull*)&mybuf[384 + 2 * k + 2];
            ull wlA0 = *(const ull*)&WlD[k * 128 + 2 * lane];
            ull wlA1 = *(const ull*)&WlD[k * 128 + 2 * lane + 64];
            ull wlB0 = *(const ull*)&WlD[(k + 1) * 128 + 2 * lane];
            ull wlB1 = *(const ull*)&WlD[(k + 1) * 128 + 2 * lane + 64];
            ull wrA0 = *(const ull*)&WrD[k * 128 + 2 * lane];
            ull wrA1 = *(const ull*)&WrD[k * 128 + 2 * lane + 64];
            ull wrB0 = *(const ull*)&WrD[(k + 1) * 128 + 2 * lane];
            ull wrB1 = *(const ull*)&WrD[(k + 1) * 128 + 2 * lane + 64];
            A00 = fma2(mA0, wlA0, A00); A00 = fma2(xA0, wrA0, A00);
            A00 = fma2(mB0, wlB0, A00); A00 = fma2(xB0, wrB0, A00);
            A10 = fma2(mA0, wlA1, A10); A10 = fma2(xA0, wrA1, A10);
            A10 = fma2(mB0, wlB1, A10); A10 = fma2(xB0, wrB1, A10);
            A01 = fma2(mA1, wlA0, A01); A01 = fma2(xA1, wrA0, A01);
            A01 = fma2(mB1, wlB0, A01); A01 = fma2(xB1, wrB0, A01);
            A11 = fma2(mA1, wlA1, A11); A11 = fma2(xA1, wrA1, A11);
            A11 = fma2(mB1, wlB1, A11); A11 = fma2(xB1, wrB1, A11);
        }
        float2 r00 = unpack2(A00);   // {node0 j=lane,    node1 j=lane}
        float2 r10 = unpack2(A10);   // {node0 j=lane+32, node1 j=lane+32}
        float2 r01 = unpack2(A01);   // {node2, node3} j=lane
        float2 r11 = unpack2(A11);   // {node2, node3} j=lane+32
        if (relu) {
            r00.x = fmaxf(r00.x, 0.f); r00.y = fmaxf(r00.y, 0.f);
            r10.x = fmaxf(r10.x, 0.f); r10.y = fmaxf(r10.y, 0.f);
            r01.x = fmaxf(r01.x, 0.f); r01.y = fmaxf(r01.y, 0.f);
            r11.x = fmaxf(r11.x, 0.f); r11.y = fmaxf(r11.y, 0.f);
        }
        hout[(long long)n0 * D + lane]            = r00.x;
        hout[(long long)(n0 + 1) * D + lane]      = r00.y;
        hout[(long long)n0 * D + 32 + lane]       = r10.x;
        hout[(long long)(n0 + 1) * D + 32 + lane] = r10.y;
        hout[(long long)(n0 + 2) * D + lane]      = r01.x;
        hout[(long long)(n0 + 3) * D + lane]      = r01.y;
        hout[(long long)(n0 + 2) * D + 32 + lane] = r11.x;
        hout[(long long)(n0 + 3) * D + 32 + lane] = r11.y;
        __syncwarp();   // buf reused next iteration
    }
}

extern "C" void kernel_launch(void* const* d_in, const int* in_sizes, int n_in,
                              void* d_out, int out_size) {
    const float* x   = (const float*)d_in[0];
    const void*  ei  = d_in[1];
    const float* Wl0 = (const float*)d_in[2];
    const float* Wr0 = (const float*)d_in[3];
    const float* b0  = (const float*)d_in[4];
    const float* Wl1 = (const float*)d_in[5];
    const float* Wr1 = (const float*)d_in[6];
    const float* b1  = (const float*)d_in[7];
    const float* Wl2 = (const float*)d_in[8];
    const float* Wr2 = (const float*)d_in[9];
    const float* b2  = (const float*)d_in[10];
    float* out = (float*)d_out;

    int E = in_sizes[1] / 2;
    int vec4 = (E % 4 == 0);
    const int SMEM_BYTES = SM_TOTAL_FLOATS * sizeof(float);   // 98816 B

    cudaFuncSetAttribute(layer_kernel,
                         cudaFuncAttributeMaxDynamicSharedMemorySize,
                         SMEM_BYTES);

    void *degp, *hAp, *hBp;
    cudaGetSymbolAddress(&degp, g_degi);
    cudaGetSymbolAddress(&hAp,  g_hA);
    cudaGetSymbolAddress(&hBp,  g_hB);
    float* hA = (float*)hAp;
    float* hB = (float*)hBp;

    const int TB = 256;
    int nwork = vec4 ? (E / 4) : E;
    int edge_blocks = (nwork + TB - 1) / TB;

    // ---- CSR build (all-parallel; graph-capturable, deterministic) ----
    cudaMemsetAsync(degp, 0, N_NODES * sizeof(int));
    detect_kernel<<<1, 32>>>(ei);
    degree_kernel<<<edge_blocks, TB>>>(ei, E, vec4);
    scan1_kernel<<<NSB, 1024>>>();
    scan2_kernel<<<1, 128>>>(NSB);
    scan3_kernel<<<NSB, 1024>>>();
    fill_kernel<<<edge_blocks, TB>>>(ei, E, vec4);

    // ---- 3 fused layers ----
    layer_kernel<<<NBLK_LAYER, LTHREADS, SMEM_BYTES>>>(x,  Wl0, Wr0, b0, hA,  1);
    layer_kernel<<<NBLK_LAYER, LTHREADS, SMEM_BYTES>>>(hA, Wl1, Wr1, b1, hB,  1);
    layer_kernel<<<NBLK_LAYER, LTHREADS, SMEM_BYTES>>>(hB, Wl2, Wr2, b2, out, 0);
}